// round 1
// baseline (speedup 1.0000x reference)
#include <cuda_runtime.h>

#define NUx 200000
#define NIx 100000
#define Dx  64
#define Ex  2000000
#define Bx  8192
#define EPSx 1e-12f

// ---- static device scratch (no allocation allowed) ----
__device__ __align__(256) float g_deg_u[NUx];
__device__ __align__(256) float g_deg_i[NIx];
__device__ __align__(256) float g_norm[Ex];
__device__ __align__(256) float g_hu0[(size_t)NUx * Dx];
__device__ __align__(256) float g_hu1[(size_t)NUx * Dx];
__device__ __align__(256) float g_hi0[(size_t)NIx * Dx];
__device__ __align__(256) float g_hi1[(size_t)NIx * Dx];
__device__ __align__(256) float g_eu [(size_t)NUx * Dx];
__device__ __align__(256) float g_ei [(size_t)NIx * Dx];

// ---- degree histogram ----
__global__ void k_deg(const int* __restrict__ eu, const int* __restrict__ ei) {
    int t = blockIdx.x * blockDim.x + threadIdx.x;
    if (t < Ex) {
        atomicAdd(&g_deg_u[eu[t]], 1.0f);
        atomicAdd(&g_deg_i[ei[t]], 1.0f);
    }
}

// ---- per-edge symmetric norm: (deg_u * deg_i)^-1/2 ----
__global__ void k_norm(const int* __restrict__ eu, const int* __restrict__ ei) {
    int t = blockIdx.x * blockDim.x + threadIdx.x;
    if (t < Ex) {
        float du = g_deg_u[eu[t]];
        float di = g_deg_i[ei[t]];
        g_norm[t] = rsqrtf(du * di);
    }
}

// ---- fused bidirectional scatter: 16 threads per edge, float4 each ----
// new_i[i] += w * hu[u];  new_u[u] += w * hi[i]
__global__ void k_scatter(const float* __restrict__ hu, const float* __restrict__ hi,
                          float* __restrict__ nu_, float* __restrict__ ni_,
                          const int* __restrict__ eu, const int* __restrict__ ei) {
    unsigned t = blockIdx.x * blockDim.x + threadIdx.x;
    unsigned e = t >> 4;
    unsigned lane = t & 15u;
    if (e >= Ex) return;
    int u = eu[e];
    int i = ei[e];
    float w = g_norm[e];

    const float4 su = *(const float4*)(hu + (size_t)u * Dx + lane * 4);
    const float4 si = *(const float4*)(hi + (size_t)i * Dx + lane * 4);

    float4 a = make_float4(w * su.x, w * su.y, w * su.z, w * su.w);
    float4 b = make_float4(w * si.x, w * si.y, w * si.z, w * si.w);

    float* pd = ni_ + (size_t)i * Dx + lane * 4;
    float* ps = nu_ + (size_t)u * Dx + lane * 4;
    asm volatile("red.global.add.v4.f32 [%0], {%1,%2,%3,%4};"
                 :: "l"(pd), "f"(a.x), "f"(a.y), "f"(a.z), "f"(a.w) : "memory");
    asm volatile("red.global.add.v4.f32 [%0], {%1,%2,%3,%4};"
                 :: "l"(ps), "f"(b.x), "f"(b.y), "f"(b.z), "f"(b.w) : "memory");
}

// ---- warp-per-row L2 normalize (in place) + e += h * coef ----
__global__ void k_normacc(float* __restrict__ h, float* __restrict__ e,
                          int rows, float coef) {
    int gw = (blockIdx.x * blockDim.x + threadIdx.x) >> 5;
    int lane = threadIdx.x & 31;
    if (gw >= rows) return;

    float2* hp = (float2*)(h + (size_t)gw * Dx) + lane;
    float2 v = *hp;
    float s = v.x * v.x + v.y * v.y;
    #pragma unroll
    for (int o = 16; o; o >>= 1) s += __shfl_xor_sync(0xFFFFFFFFu, s, o);
    float inv = 1.0f / fmaxf(sqrtf(s), EPSx);
    v.x *= inv; v.y *= inv;
    *hp = v;

    float2* ep = (float2*)(e + (size_t)gw * Dx) + lane;
    float2 ev = *ep;
    ev.x += v.x * coef;
    ev.y += v.y * coef;
    *ep = ev;
}

// ---- final gather of (ue[users], ie[pos], ie[neg]) -> out [3][B][D] ----
__global__ void k_out(const int* __restrict__ users, const int* __restrict__ pos,
                      const int* __restrict__ neg, float* __restrict__ out) {
    unsigned t = blockIdx.x * blockDim.x + threadIdx.x;
    unsigned r = t >> 4;
    unsigned lane = t & 15u;
    if (r >= 3u * Bx) return;
    unsigned grp = r / Bx, idx = r % Bx;
    const float* src;
    if (grp == 0)      src = g_eu + (size_t)users[idx] * Dx;
    else if (grp == 1) src = g_ei + (size_t)pos[idx]   * Dx;
    else               src = g_ei + (size_t)neg[idx]   * Dx;
    *(float4*)(out + (size_t)r * Dx + lane * 4) = *(const float4*)(src + lane * 4);
}

extern "C" void kernel_launch(void* const* d_in, const int* in_sizes, int n_in,
                              void* d_out, int out_size) {
    const float* uf   = (const float*)d_in[0];
    const float* itf  = (const float*)d_in[1];
    const int*   eu   = (const int*)d_in[2];
    const int*   ei   = (const int*)d_in[3];
    const int*   usr  = (const int*)d_in[4];
    const int*   pos  = (const int*)d_in[5];
    const int*   neg  = (const int*)d_in[6];
    float* out = (float*)d_out;

    void *p_deg_u, *p_deg_i, *p_hu0, *p_hu1, *p_hi0, *p_hi1, *p_eu, *p_ei;
    cudaGetSymbolAddress(&p_deg_u, g_deg_u);
    cudaGetSymbolAddress(&p_deg_i, g_deg_i);
    cudaGetSymbolAddress(&p_hu0, g_hu0);
    cudaGetSymbolAddress(&p_hu1, g_hu1);
    cudaGetSymbolAddress(&p_hi0, g_hi0);
    cudaGetSymbolAddress(&p_hi1, g_hi1);
    cudaGetSymbolAddress(&p_eu, g_eu);
    cudaGetSymbolAddress(&p_ei, g_ei);

    const size_t huB = (size_t)NUx * Dx * sizeof(float);
    const size_t hiB = (size_t)NIx * Dx * sizeof(float);

    // degrees + per-edge norm
    cudaMemsetAsync(p_deg_u, 0, NUx * sizeof(float));
    cudaMemsetAsync(p_deg_i, 0, NIx * sizeof(float));
    k_deg <<<(Ex + 255) / 256, 256>>>(eu, ei);
    k_norm<<<(Ex + 255) / 256, 256>>>(eu, ei);

    // e accumulators start at input features
    cudaMemcpyAsync(p_eu, uf,  huB, cudaMemcpyDeviceToDevice);
    cudaMemcpyAsync(p_ei, itf, hiB, cudaMemcpyDeviceToDevice);

    const unsigned scat_blocks = (unsigned)(((size_t)Ex * 16 + 255) / 256);
    const unsigned nu_blocks = (unsigned)(((size_t)NUx * 32 + 255) / 256);
    const unsigned ni_blocks = (unsigned)(((size_t)NIx * 32 + 255) / 256);

    // ---- layer 0: src = inputs, dst = buf0, coef = 1 ----
    cudaMemsetAsync(p_hu0, 0, huB);
    cudaMemsetAsync(p_hi0, 0, hiB);
    k_scatter<<<scat_blocks, 256>>>(uf, itf, (float*)p_hu0, (float*)p_hi0, eu, ei);
    k_normacc<<<nu_blocks, 256>>>((float*)p_hu0, (float*)p_eu, NUx, 1.0f);
    k_normacc<<<ni_blocks, 256>>>((float*)p_hi0, (float*)p_ei, NIx, 1.0f);

    // ---- layer 1: src = buf0, dst = buf1, coef = 1/2 ----
    cudaMemsetAsync(p_hu1, 0, huB);
    cudaMemsetAsync(p_hi1, 0, hiB);
    k_scatter<<<scat_blocks, 256>>>((const float*)p_hu0, (const float*)p_hi0,
                                    (float*)p_hu1, (float*)p_hi1, eu, ei);
    k_normacc<<<nu_blocks, 256>>>((float*)p_hu1, (float*)p_eu, NUx, 0.5f);
    k_normacc<<<ni_blocks, 256>>>((float*)p_hi1, (float*)p_ei, NIx, 0.5f);

    // ---- layer 2: src = buf1, dst = buf0, coef = 1/3 ----
    cudaMemsetAsync(p_hu0, 0, huB);
    cudaMemsetAsync(p_hi0, 0, hiB);
    k_scatter<<<scat_blocks, 256>>>((const float*)p_hu1, (const float*)p_hi1,
                                    (float*)p_hu0, (float*)p_hi0, eu, ei);
    k_normacc<<<nu_blocks, 256>>>((float*)p_hu0, (float*)p_eu, NUx, 1.0f / 3.0f);
    k_normacc<<<ni_blocks, 256>>>((float*)p_hi0, (float*)p_ei, NIx, 1.0f / 3.0f);

    // ---- output gather ----
    k_out<<<(3 * Bx * 16 + 255) / 256, 256>>>(usr, pos, neg, out);
}

// round 2
// speedup vs baseline: 1.5464x; 1.5464x over previous
#include <cuda_runtime.h>

#define NUx 200000
#define NIx 100000
#define Dx  64
#define Ex  2000000
#define Bx  8192
#define EPSx 1e-12f

#define SB 256
#define SI 8                 // 2048 elements per scan block
#define NW (SB/32)

// ---- static device scratch (no allocation allowed) ----
__device__ int g_deg_u[NUx];
__device__ int g_deg_i[NIx];
__device__ int g_off_u[NUx];
__device__ int g_off_i[NIx];
__device__ int g_cur_u[NUx];
__device__ int g_cur_i[NIx];
__device__ int g_bsum_u[128];
__device__ int g_bsum_i[128];
__device__ __align__(16) int2 g_adj_u[Ex];   // per-user list: (item, w)
__device__ __align__(16) int2 g_adj_i[Ex];   // per-item list: (user, w)
__device__ __align__(256) float g_hu0[(size_t)NUx * Dx];
__device__ __align__(256) float g_hu1[(size_t)NUx * Dx];
__device__ __align__(256) float g_hi0[(size_t)NIx * Dx];
__device__ __align__(256) float g_hi1[(size_t)NIx * Dx];
__device__ __align__(256) float g_eu [(size_t)NUx * Dx];
__device__ __align__(256) float g_ei [(size_t)NIx * Dx];

// ---- degree histogram (int) ----
__global__ void k_deg(const int* __restrict__ eu, const int* __restrict__ ei) {
    int t = blockIdx.x * blockDim.x + threadIdx.x;
    if (t < Ex) {
        atomicAdd(&g_deg_u[eu[t]], 1);
        atomicAdd(&g_deg_i[ei[t]], 1);
    }
}

// ---- exclusive scan, stage 1: per-block scan + block sums ----
__global__ void k_scan_blocks(const int* __restrict__ in, int* __restrict__ out,
                              int* __restrict__ bsum, int n) {
    __shared__ int warp_tot[NW];
    int lane = threadIdx.x & 31, wid = threadIdx.x >> 5;
    int base = blockIdx.x * (SB * SI) + threadIdx.x * SI;

    int v[SI];
    int s = 0;
    #pragma unroll
    for (int k = 0; k < SI; ++k) {
        int idx = base + k;
        v[k] = (idx < n) ? in[idx] : 0;
        s += v[k];
    }
    int ps = s;  // inclusive warp scan of thread totals
    #pragma unroll
    for (int o = 1; o < 32; o <<= 1) {
        int t = __shfl_up_sync(0xffffffffu, ps, o);
        if (lane >= o) ps += t;
    }
    if (lane == 31) warp_tot[wid] = ps;
    __syncthreads();
    if (wid == 0) {
        int wt = (lane < NW) ? warp_tot[lane] : 0;
        int wps = wt;
        #pragma unroll
        for (int o = 1; o < NW; o <<= 1) {
            int t = __shfl_up_sync(0xffffffffu, wps, o);
            if (lane >= o) wps += t;
        }
        if (lane < NW) warp_tot[lane] = wps - wt;  // exclusive warp prefix
    }
    __syncthreads();
    int excl = warp_tot[wid] + (ps - s);
    int run = excl;
    #pragma unroll
    for (int k = 0; k < SI; ++k) {
        int idx = base + k;
        if (idx < n) out[idx] = run;   // exclusive
        run += v[k];
    }
    if (threadIdx.x == SB - 1) bsum[blockIdx.x] = excl + s;  // block total
}

// ---- exclusive scan of the (<=128) block sums, in place ----
__global__ void k_scan_small(int* __restrict__ b, int n) {
    __shared__ int wt[4];
    int tid = threadIdx.x;
    int lane = tid & 31, wid = tid >> 5;
    int v = (tid < n) ? b[tid] : 0;
    int ps = v;
    #pragma unroll
    for (int o = 1; o < 32; o <<= 1) {
        int t = __shfl_up_sync(0xffffffffu, ps, o);
        if (lane >= o) ps += t;
    }
    if (lane == 31) wt[wid] = ps;
    __syncthreads();
    if (tid == 0) {
        int r = 0;
        #pragma unroll
        for (int k = 0; k < 4; ++k) { int t = wt[k]; wt[k] = r; r += t; }
    }
    __syncthreads();
    if (tid < n) b[tid] = wt[wid] + ps - v;  // exclusive
}

// ---- scan stage 3: add block offsets; also init cursor copy ----
__global__ void k_scan_add(int* __restrict__ out, int* __restrict__ cur,
                           const int* __restrict__ bsum, int n) {
    int base = blockIdx.x * (SB * SI) + threadIdx.x * SI;
    int add = bsum[blockIdx.x];
    #pragma unroll
    for (int k = 0; k < SI; ++k) {
        int idx = base + k;
        if (idx < n) {
            int val = out[idx] + add;
            out[idx] = val;
            cur[idx] = val;
        }
    }
}

// ---- counting-sort fill of both adjacency lists + per-edge norm ----
__global__ void k_fill(const int* __restrict__ eu, const int* __restrict__ ei) {
    int e = blockIdx.x * blockDim.x + threadIdx.x;
    if (e >= Ex) return;
    int u = eu[e], i = ei[e];
    float w = rsqrtf((float)(g_deg_u[u] * g_deg_i[i]));
    int wb = __float_as_int(w);
    int pu = atomicAdd(&g_cur_u[u], 1);
    g_adj_u[pu] = make_int2(i, wb);
    int pi = atomicAdd(&g_cur_i[i], 1);
    g_adj_i[pi] = make_int2(u, wb);
}

// ---- warp-per-row gather-aggregate + fused L2-normalize + e accumulate ----
// hout[row] = l2norm( sum_j w_j * src[nbr_j] );  eout[row] = ein[row] + coef*hout[row]
__global__ void k_agg(const float* __restrict__ src,
                      float* __restrict__ hout,
                      const float* ein, float* eout,
                      const int* __restrict__ off,
                      const int2* __restrict__ adj,
                      int nrows, float coef) {
    __shared__ int2 sh[NW][32];
    int gw = (blockIdx.x * blockDim.x + threadIdx.x) >> 5;
    int lane = threadIdx.x & 31;
    int wid = threadIdx.x >> 5;
    if (gw >= nrows) return;

    int beg = off[gw];
    int end = (gw + 1 < nrows) ? off[gw + 1] : Ex;

    const float2* sv = (const float2*)src;
    float2 acc = make_float2(0.f, 0.f);

    for (int p = beg; p < end; p += 32) {
        if (p + lane < end) sh[wid][lane] = adj[p + lane];
        __syncwarp();
        int c = min(end - p, 32);
        int j = 0;
        for (; j + 4 <= c; j += 4) {
            int2 a0 = sh[wid][j + 0];
            int2 a1 = sh[wid][j + 1];
            int2 a2 = sh[wid][j + 2];
            int2 a3 = sh[wid][j + 3];
            float2 v0 = sv[(size_t)a0.x * 32 + lane];
            float2 v1 = sv[(size_t)a1.x * 32 + lane];
            float2 v2 = sv[(size_t)a2.x * 32 + lane];
            float2 v3 = sv[(size_t)a3.x * 32 + lane];
            float w0 = __int_as_float(a0.y);
            float w1 = __int_as_float(a1.y);
            float w2 = __int_as_float(a2.y);
            float w3 = __int_as_float(a3.y);
            acc.x += w0 * v0.x; acc.y += w0 * v0.y;
            acc.x += w1 * v1.x; acc.y += w1 * v1.y;
            acc.x += w2 * v2.x; acc.y += w2 * v2.y;
            acc.x += w3 * v3.x; acc.y += w3 * v3.y;
        }
        for (; j < c; ++j) {
            int2 a = sh[wid][j];
            float2 v = sv[(size_t)a.x * 32 + lane];
            float w = __int_as_float(a.y);
            acc.x += w * v.x; acc.y += w * v.y;
        }
        __syncwarp();
    }

    float s = acc.x * acc.x + acc.y * acc.y;
    #pragma unroll
    for (int o = 16; o; o >>= 1) s += __shfl_xor_sync(0xffffffffu, s, o);
    float inv = 1.0f / fmaxf(sqrtf(s), EPSx);
    float2 h = make_float2(acc.x * inv, acc.y * inv);

    ((float2*)hout)[(size_t)gw * 32 + lane] = h;
    float2 ev = ((const float2*)ein)[(size_t)gw * 32 + lane];
    ev.x += h.x * coef;
    ev.y += h.y * coef;
    ((float2*)eout)[(size_t)gw * 32 + lane] = ev;
}

// ---- final gather of (ue[users], ie[pos], ie[neg]) -> out [3][B][D] ----
__global__ void k_out(const int* __restrict__ users, const int* __restrict__ pos,
                      const int* __restrict__ neg, float* __restrict__ out) {
    unsigned t = blockIdx.x * blockDim.x + threadIdx.x;
    unsigned r = t >> 4;
    unsigned lane = t & 15u;
    if (r >= 3u * Bx) return;
    unsigned grp = r / Bx, idx = r % Bx;
    const float* src;
    if (grp == 0)      src = g_eu + (size_t)users[idx] * Dx;
    else if (grp == 1) src = g_ei + (size_t)pos[idx]   * Dx;
    else               src = g_ei + (size_t)neg[idx]   * Dx;
    *(float4*)(out + (size_t)r * Dx + lane * 4) = *(const float4*)(src + lane * 4);
}

extern "C" void kernel_launch(void* const* d_in, const int* in_sizes, int n_in,
                              void* d_out, int out_size) {
    const float* uf  = (const float*)d_in[0];
    const float* itf = (const float*)d_in[1];
    const int*   eu  = (const int*)d_in[2];
    const int*   ei  = (const int*)d_in[3];
    const int*   usr = (const int*)d_in[4];
    const int*   pos = (const int*)d_in[5];
    const int*   neg = (const int*)d_in[6];
    float* out = (float*)d_out;

    void *p_deg_u, *p_deg_i, *p_off_u, *p_off_i, *p_cur_u, *p_cur_i;
    void *p_bsum_u, *p_bsum_i, *p_adj_u, *p_adj_i;
    void *p_hu0, *p_hu1, *p_hi0, *p_hi1, *p_eu, *p_ei;
    cudaGetSymbolAddress(&p_deg_u, g_deg_u);
    cudaGetSymbolAddress(&p_deg_i, g_deg_i);
    cudaGetSymbolAddress(&p_off_u, g_off_u);
    cudaGetSymbolAddress(&p_off_i, g_off_i);
    cudaGetSymbolAddress(&p_cur_u, g_cur_u);
    cudaGetSymbolAddress(&p_cur_i, g_cur_i);
    cudaGetSymbolAddress(&p_bsum_u, g_bsum_u);
    cudaGetSymbolAddress(&p_bsum_i, g_bsum_i);
    cudaGetSymbolAddress(&p_adj_u, g_adj_u);
    cudaGetSymbolAddress(&p_adj_i, g_adj_i);
    cudaGetSymbolAddress(&p_hu0, g_hu0);
    cudaGetSymbolAddress(&p_hu1, g_hu1);
    cudaGetSymbolAddress(&p_hi0, g_hi0);
    cudaGetSymbolAddress(&p_hi1, g_hi1);
    cudaGetSymbolAddress(&p_eu, g_eu);
    cudaGetSymbolAddress(&p_ei, g_ei);

    const int scanb_u = (NUx + SB * SI - 1) / (SB * SI);   // 98
    const int scanb_i = (NIx + SB * SI - 1) / (SB * SI);   // 49

    // ---- CSR build ----
    cudaMemsetAsync(p_deg_u, 0, NUx * sizeof(int));
    cudaMemsetAsync(p_deg_i, 0, NIx * sizeof(int));
    k_deg<<<(Ex + 255) / 256, 256>>>(eu, ei);
    k_scan_blocks<<<scanb_u, SB>>>((const int*)p_deg_u, (int*)p_off_u, (int*)p_bsum_u, NUx);
    k_scan_blocks<<<scanb_i, SB>>>((const int*)p_deg_i, (int*)p_off_i, (int*)p_bsum_i, NIx);
    k_scan_small<<<1, 128>>>((int*)p_bsum_u, scanb_u);
    k_scan_small<<<1, 128>>>((int*)p_bsum_i, scanb_i);
    k_scan_add<<<scanb_u, SB>>>((int*)p_off_u, (int*)p_cur_u, (const int*)p_bsum_u, NUx);
    k_scan_add<<<scanb_i, SB>>>((int*)p_off_i, (int*)p_cur_i, (const int*)p_bsum_i, NIx);
    k_fill<<<(Ex + 255) / 256, 256>>>(eu, ei);

    const unsigned gi = (NIx * 32 + 255) / 256;   // warp per item row
    const unsigned gu = (NUx * 32 + 255) / 256;   // warp per user row

    // ---- layer 0: src = inputs; e init = inputs; coef = 1 ----
    k_agg<<<gi, 256>>>(uf,  (float*)p_hi0, itf, (float*)p_ei,
                       (const int*)p_off_i, (const int2*)p_adj_i, NIx, 1.0f);
    k_agg<<<gu, 256>>>(itf, (float*)p_hu0, uf,  (float*)p_eu,
                       (const int*)p_off_u, (const int2*)p_adj_u, NUx, 1.0f);

    // ---- layer 1: coef = 1/2 ----
    k_agg<<<gi, 256>>>((const float*)p_hu0, (float*)p_hi1, (const float*)p_ei, (float*)p_ei,
                       (const int*)p_off_i, (const int2*)p_adj_i, NIx, 0.5f);
    k_agg<<<gu, 256>>>((const float*)p_hi0, (float*)p_hu1, (const float*)p_eu, (float*)p_eu,
                       (const int*)p_off_u, (const int2*)p_adj_u, NUx, 0.5f);

    // ---- layer 2: coef = 1/3 ----
    k_agg<<<gi, 256>>>((const float*)p_hu1, (float*)p_hi0, (const float*)p_ei, (float*)p_ei,
                       (const int*)p_off_i, (const int2*)p_adj_i, NIx, 1.0f / 3.0f);
    k_agg<<<gu, 256>>>((const float*)p_hi1, (float*)p_hu0, (const float*)p_eu, (float*)p_eu,
                       (const int*)p_off_u, (const int2*)p_adj_u, NUx, 1.0f / 3.0f);

    // ---- output gather ----
    k_out<<<(3 * Bx * 16 + 255) / 256, 256>>>(usr, pos, neg, out);
}

// round 3
// speedup vs baseline: 1.9555x; 1.2646x over previous
#include <cuda_runtime.h>
#include <cuda_fp16.h>

#define NUx 200000
#define NIx 100000
#define Dx  64
#define Ex  2000000
#define Bx  8192
#define EPSx 1e-12f

#define SB 256
#define SI 8                 // 2048 elements per scan block
#define NW (SB/32)

// ---- static device scratch (no allocation allowed) ----
__device__ int g_deg_u[NUx];
__device__ int g_deg_i[NIx];
__device__ int g_off_u[NUx];
__device__ int g_off_i[NIx];
__device__ int g_cur_u[NUx];
__device__ int g_cur_i[NIx];
__device__ int g_bsum_u[128];
__device__ int g_bsum_i[128];
__device__ __align__(16) int2 g_adj_u[Ex];   // per-user list: (item, w)
__device__ __align__(16) int2 g_adj_i[Ex];   // per-item list: (user, w)

// fp16 feature storage: inputs + 3 layer outputs per side (rows of 32 half2)
__device__ __align__(256) __half2 g_uf16[(size_t)NUx * 32];
__device__ __align__(256) __half2 g_if16[(size_t)NIx * 32];
__device__ __align__(256) __half2 g_hu16[3][(size_t)NUx * 32];
__device__ __align__(256) __half2 g_hi16[3][(size_t)NIx * 32];

// ---- degree histogram (int) ----
__global__ void k_deg(const int* __restrict__ eu, const int* __restrict__ ei) {
    int t = blockIdx.x * blockDim.x + threadIdx.x;
    if (t < Ex) {
        atomicAdd(&g_deg_u[eu[t]], 1);
        atomicAdd(&g_deg_i[ei[t]], 1);
    }
}

// ---- exclusive scan, stage 1: per-block scan + block sums ----
__global__ void k_scan_blocks(const int* __restrict__ in, int* __restrict__ out,
                              int* __restrict__ bsum, int n) {
    __shared__ int warp_tot[NW];
    int lane = threadIdx.x & 31, wid = threadIdx.x >> 5;
    int base = blockIdx.x * (SB * SI) + threadIdx.x * SI;

    int v[SI];
    int s = 0;
    #pragma unroll
    for (int k = 0; k < SI; ++k) {
        int idx = base + k;
        v[k] = (idx < n) ? in[idx] : 0;
        s += v[k];
    }
    int ps = s;
    #pragma unroll
    for (int o = 1; o < 32; o <<= 1) {
        int t = __shfl_up_sync(0xffffffffu, ps, o);
        if (lane >= o) ps += t;
    }
    if (lane == 31) warp_tot[wid] = ps;
    __syncthreads();
    if (wid == 0) {
        int wt = (lane < NW) ? warp_tot[lane] : 0;
        int wps = wt;
        #pragma unroll
        for (int o = 1; o < NW; o <<= 1) {
            int t = __shfl_up_sync(0xffffffffu, wps, o);
            if (lane >= o) wps += t;
        }
        if (lane < NW) warp_tot[lane] = wps - wt;
    }
    __syncthreads();
    int excl = warp_tot[wid] + (ps - s);
    int run = excl;
    #pragma unroll
    for (int k = 0; k < SI; ++k) {
        int idx = base + k;
        if (idx < n) out[idx] = run;
        run += v[k];
    }
    if (threadIdx.x == SB - 1) bsum[blockIdx.x] = excl + s;
}

// ---- exclusive scan of both block-sum arrays in one launch ----
__global__ void k_scan_small2(int* __restrict__ bu, int nu_,
                              int* __restrict__ bi, int ni_) {
    int* b = blockIdx.x ? bi : bu;
    int n  = blockIdx.x ? ni_ : nu_;
    __shared__ int wt[4];
    int tid = threadIdx.x;
    int lane = tid & 31, wid = tid >> 5;
    int v = (tid < n) ? b[tid] : 0;
    int ps = v;
    #pragma unroll
    for (int o = 1; o < 32; o <<= 1) {
        int t = __shfl_up_sync(0xffffffffu, ps, o);
        if (lane >= o) ps += t;
    }
    if (lane == 31) wt[wid] = ps;
    __syncthreads();
    if (tid == 0) {
        int r = 0;
        #pragma unroll
        for (int k = 0; k < 4; ++k) { int t = wt[k]; wt[k] = r; r += t; }
    }
    __syncthreads();
    if (tid < n) b[tid] = wt[wid] + ps - v;
}

// ---- scan stage 3: add block offsets; also init cursor copy ----
__global__ void k_scan_add(int* __restrict__ out, int* __restrict__ cur,
                           const int* __restrict__ bsum, int n) {
    int base = blockIdx.x * (SB * SI) + threadIdx.x * SI;
    int add = bsum[blockIdx.x];
    #pragma unroll
    for (int k = 0; k < SI; ++k) {
        int idx = base + k;
        if (idx < n) {
            int val = out[idx] + add;
            out[idx] = val;
            cur[idx] = val;
        }
    }
}

// ---- counting-sort fill of both adjacency lists + per-edge norm ----
__global__ void k_fill(const int* __restrict__ eu, const int* __restrict__ ei) {
    int e = blockIdx.x * blockDim.x + threadIdx.x;
    if (e >= Ex) return;
    int u = eu[e], i = ei[e];
    float w = rsqrtf((float)(g_deg_u[u] * g_deg_i[i]));
    int wb = __float_as_int(w);
    int pu = atomicAdd(&g_cur_u[u], 1);
    g_adj_u[pu] = make_int2(i, wb);
    int pi = atomicAdd(&g_cur_i[i], 1);
    g_adj_i[pi] = make_int2(u, wb);
}

// ---- convert fp32 inputs to fp16 staging ----
__global__ void k_cvt(const float* __restrict__ uf, const float* __restrict__ itf) {
    int t = blockIdx.x * blockDim.x + threadIdx.x;
    if (t < NUx * 32) {
        float2 f = ((const float2*)uf)[t];
        g_uf16[t] = __float22half2_rn(f);
    } else if (t < (NUx + NIx) * 32) {
        int s = t - NUx * 32;
        float2 f = ((const float2*)itf)[s];
        g_if16[s] = __float22half2_rn(f);
    }
}

// ---- merged both-direction gather-aggregate + fused L2-normalize ----
// rows [0, NI): item dest, gather user rows. rows [NI, NI+NU): user dest.
__global__ void k_agg(const __half2* __restrict__ srcU,
                      const __half2* __restrict__ srcI,
                      __half2* __restrict__ houtU,
                      __half2* __restrict__ houtI) {
    __shared__ int2 sh[NW][32];
    int gw = (blockIdx.x * blockDim.x + threadIdx.x) >> 5;
    int lane = threadIdx.x & 31;
    int wid = threadIdx.x >> 5;
    if (gw >= NIx + NUx) return;

    const __half2* src;
    __half2* hout;
    const int2* adj;
    int beg, end, row;
    if (gw < NIx) {
        row = gw;
        src = srcU; hout = houtI; adj = g_adj_i;
        beg = g_off_i[row];
        end = (row + 1 < NIx) ? g_off_i[row + 1] : Ex;
    } else {
        row = gw - NIx;
        src = srcI; hout = houtU; adj = g_adj_u;
        beg = g_off_u[row];
        end = (row + 1 < NUx) ? g_off_u[row + 1] : Ex;
    }

    float2 acc = make_float2(0.f, 0.f);

    for (int p = beg; p < end; p += 32) {
        if (p + lane < end) sh[wid][lane] = adj[p + lane];
        __syncwarp();
        int c = min(end - p, 32);
        int j = 0;
        for (; j + 4 <= c; j += 4) {
            int2 a0 = sh[wid][j + 0];
            int2 a1 = sh[wid][j + 1];
            int2 a2 = sh[wid][j + 2];
            int2 a3 = sh[wid][j + 3];
            float2 v0 = __half22float2(src[(size_t)a0.x * 32 + lane]);
            float2 v1 = __half22float2(src[(size_t)a1.x * 32 + lane]);
            float2 v2 = __half22float2(src[(size_t)a2.x * 32 + lane]);
            float2 v3 = __half22float2(src[(size_t)a3.x * 32 + lane]);
            float w0 = __int_as_float(a0.y);
            float w1 = __int_as_float(a1.y);
            float w2 = __int_as_float(a2.y);
            float w3 = __int_as_float(a3.y);
            acc.x += w0 * v0.x; acc.y += w0 * v0.y;
            acc.x += w1 * v1.x; acc.y += w1 * v1.y;
            acc.x += w2 * v2.x; acc.y += w2 * v2.y;
            acc.x += w3 * v3.x; acc.y += w3 * v3.y;
        }
        for (; j < c; ++j) {
            int2 a = sh[wid][j];
            float2 v = __half22float2(src[(size_t)a.x * 32 + lane]);
            float w = __int_as_float(a.y);
            acc.x += w * v.x; acc.y += w * v.y;
        }
        __syncwarp();
    }

    float s = acc.x * acc.x + acc.y * acc.y;
    #pragma unroll
    for (int o = 16; o; o >>= 1) s += __shfl_xor_sync(0xffffffffu, s, o);
    float inv = 1.0f / fmaxf(sqrtf(s), EPSx);

    hout[(size_t)row * 32 + lane] =
        __float22half2_rn(make_float2(acc.x * inv, acc.y * inv));
}

// ---- final gather: e = f + h0 + h1/2 + h2/3 at sampled rows ----
__global__ void k_out(const float* __restrict__ uf, const float* __restrict__ itf,
                      const int* __restrict__ users, const int* __restrict__ pos,
                      const int* __restrict__ neg, float* __restrict__ out) {
    unsigned t = blockIdx.x * blockDim.x + threadIdx.x;
    unsigned r = t >> 4;
    unsigned lane = t & 15u;          // 16 lanes x 4 floats = 64 cols
    if (r >= 3u * Bx) return;
    unsigned grp = r / Bx, idx = r % Bx;

    const float* base;
    const __half2 *h0, *h1, *h2;
    size_t row;
    if (grp == 0) {
        row = (size_t)users[idx];
        base = uf + row * Dx;
        h0 = g_hu16[0] + row * 32; h1 = g_hu16[1] + row * 32; h2 = g_hu16[2] + row * 32;
    } else {
        row = (size_t)((grp == 1) ? pos[idx] : neg[idx]);
        base = itf + row * Dx;
        h0 = g_hi16[0] + row * 32; h1 = g_hi16[1] + row * 32; h2 = g_hi16[2] + row * 32;
    }

    float4 f = *(const float4*)(base + lane * 4);
    float2 a0 = __half22float2(h0[lane * 2]), b0 = __half22float2(h0[lane * 2 + 1]);
    float2 a1 = __half22float2(h1[lane * 2]), b1 = __half22float2(h1[lane * 2 + 1]);
    float2 a2 = __half22float2(h2[lane * 2]), b2 = __half22float2(h2[lane * 2 + 1]);

    const float c1 = 0.5f, c2 = 1.0f / 3.0f;
    f.x += a0.x + c1 * a1.x + c2 * a2.x;
    f.y += a0.y + c1 * a1.y + c2 * a2.y;
    f.z += b0.x + c1 * b1.x + c2 * b2.x;
    f.w += b0.y + c1 * b1.y + c2 * b2.y;

    *(float4*)(out + (size_t)r * Dx + lane * 4) = f;
}

extern "C" void kernel_launch(void* const* d_in, const int* in_sizes, int n_in,
                              void* d_out, int out_size) {
    const float* uf  = (const float*)d_in[0];
    const float* itf = (const float*)d_in[1];
    const int*   eu  = (const int*)d_in[2];
    const int*   ei  = (const int*)d_in[3];
    const int*   usr = (const int*)d_in[4];
    const int*   pos = (const int*)d_in[5];
    const int*   neg = (const int*)d_in[6];
    float* out = (float*)d_out;

    void *p_deg_u, *p_deg_i, *p_off_u, *p_off_i, *p_cur_u, *p_cur_i;
    void *p_bsum_u, *p_bsum_i;
    void *p_uf16, *p_if16, *p_hu[3], *p_hi[3];
    cudaGetSymbolAddress(&p_deg_u, g_deg_u);
    cudaGetSymbolAddress(&p_deg_i, g_deg_i);
    cudaGetSymbolAddress(&p_off_u, g_off_u);
    cudaGetSymbolAddress(&p_off_i, g_off_i);
    cudaGetSymbolAddress(&p_cur_u, g_cur_u);
    cudaGetSymbolAddress(&p_cur_i, g_cur_i);
    cudaGetSymbolAddress(&p_bsum_u, g_bsum_u);
    cudaGetSymbolAddress(&p_bsum_i, g_bsum_i);
    cudaGetSymbolAddress(&p_uf16, g_uf16);
    cudaGetSymbolAddress(&p_if16, g_if16);
    {
        void* tmp;
        cudaGetSymbolAddress(&tmp, g_hu16);
        for (int k = 0; k < 3; ++k) p_hu[k] = (char*)tmp + (size_t)k * NUx * 32 * sizeof(__half2);
        cudaGetSymbolAddress(&tmp, g_hi16);
        for (int k = 0; k < 3; ++k) p_hi[k] = (char*)tmp + (size_t)k * NIx * 32 * sizeof(__half2);
    }

    const int scanb_u = (NUx + SB * SI - 1) / (SB * SI);   // 98
    const int scanb_i = (NIx + SB * SI - 1) / (SB * SI);   // 49

    // ---- CSR build + fp16 input staging ----
    cudaMemsetAsync(p_deg_u, 0, NUx * sizeof(int));
    cudaMemsetAsync(p_deg_i, 0, NIx * sizeof(int));
    k_deg<<<(Ex + 255) / 256, 256>>>(eu, ei);
    k_cvt<<<((NUx + NIx) * 32 + 255) / 256, 256>>>(uf, itf);
    k_scan_blocks<<<scanb_u, SB>>>((const int*)p_deg_u, (int*)p_off_u, (int*)p_bsum_u, NUx);
    k_scan_blocks<<<scanb_i, SB>>>((const int*)p_deg_i, (int*)p_off_i, (int*)p_bsum_i, NIx);
    k_scan_small2<<<2, 128>>>((int*)p_bsum_u, scanb_u, (int*)p_bsum_i, scanb_i);
    k_scan_add<<<scanb_u, SB>>>((int*)p_off_u, (int*)p_cur_u, (const int*)p_bsum_u, NUx);
    k_scan_add<<<scanb_i, SB>>>((int*)p_off_i, (int*)p_cur_i, (const int*)p_bsum_i, NIx);
    k_fill<<<(Ex + 255) / 256, 256>>>(eu, ei);

    const unsigned gagg = (unsigned)(((size_t)(NUx + NIx) * 32 + 255) / 256);

    // ---- 3 propagation layers (both directions merged per launch) ----
    k_agg<<<gagg, 256>>>((const __half2*)p_uf16, (const __half2*)p_if16,
                         (__half2*)p_hu[0], (__half2*)p_hi[0]);
    k_agg<<<gagg, 256>>>((const __half2*)p_hu[0], (const __half2*)p_hi[0],
                         (__half2*)p_hu[1], (__half2*)p_hi[1]);
    k_agg<<<gagg, 256>>>((const __half2*)p_hu[1], (const __half2*)p_hi[1],
                         (__half2*)p_hu[2], (__half2*)p_hi[2]);

    // ---- output gather (e computed on the fly) ----
    k_out<<<(3 * Bx * 16 + 255) / 256, 256>>>(uf, itf, usr, pos, neg, out);
}